// round 2
// baseline (speedup 1.0000x reference)
#include <cuda_runtime.h>
#include <cuda_bf16.h>
#include <cstdint>

// Problem constants
#define N_ANCH   8192
#define DIM      64
#define NSPLIT   8          // j-dimension splits for the mining kernel
#define ITILE    256        // anchors per mining CTA (== blockDim)
#define NITILES  (N_ANCH / ITILE)          // 32
#define JRANGE   (N_ANCH / NSPLIT)         // 1024 j per split
#define TJ       128        // j-chunk staged in smem
#define MARGIN_F 0.5f
#define RBLOCKS  (N_ANCH / 256)            // 32 reduce blocks

// Device scratch (no allocations allowed in kernel_launch)
__device__ float g_sq[N_ANCH];
__device__ float g_maxval[NSPLIT * N_ANCH];
__device__ int   g_maxidx[NSPLIT * N_ANCH];
__device__ float g_minval[NSPLIT * N_ANCH];
__device__ int   g_minidx[NSPLIT * N_ANCH];
__device__ float g_partial[RBLOCKS];

// Packed fp32x2 FMA (sm_103a): d = a*b + c on two independent fp32 lanes.
#define FMA2(d, a, b, c) \
    asm("fma.rn.f32x2 %0, %1, %2, %3;" : "=l"(d) : "l"(a), "l"(b), "l"(c))
#define UNPACK2(lo, hi, v) \
    asm("mov.b64 {%0, %1}, %2;" : "=f"(lo), "=f"(hi) : "l"(v))

// ---------------------------------------------------------------------------
// Kernel 0: per-row squared norms
// ---------------------------------------------------------------------------
__global__ void sqnorm_kernel(const float* __restrict__ emb) {
    int i = blockIdx.x * blockDim.x + threadIdx.x;
    if (i >= N_ANCH) return;
    const float4* r = reinterpret_cast<const float4*>(emb + (size_t)i * DIM);
    float s = 0.f;
#pragma unroll
    for (int k = 0; k < DIM / 4; k++) {
        float4 v = r[k];
        s += v.x * v.x + v.y * v.y + v.z * v.z + v.w * v.w;
    }
    g_sq[i] = s;
}

// ---------------------------------------------------------------------------
// Kernel 1: batch-hard mining.
// grid = (NITILES, NSPLIT); block = ITILE threads, one anchor per thread.
// Each block scans j in [split*JRANGE, (split+1)*JRANGE) ascending, tracking
// first-occurrence argmax over same-class dists and argmin over other-class.
// ---------------------------------------------------------------------------
__global__ __launch_bounds__(ITILE, 2)
void mine_kernel(const float* __restrict__ emb,
                 const int* __restrict__ tgt) {
    __shared__ float4 s_emb4[TJ * (DIM / 4)];   // 32 KB
    __shared__ int    s_tgt[TJ];
    __shared__ float  s_sq[TJ];

    const int itile = blockIdx.x;
    const int split = blockIdx.y;
    const int i = itile * ITILE + threadIdx.x;

    // Anchor row in registers as 32 packed fp32 pairs (b64 each).
    unsigned long long a[DIM / 2];
    {
        const ulonglong2* ar =
            reinterpret_cast<const ulonglong2*>(emb + (size_t)i * DIM);
#pragma unroll
        for (int k = 0; k < DIM / 4; k++) {
            ulonglong2 v = ar[k];
            a[2 * k]     = v.x;
            a[2 * k + 1] = v.y;
        }
    }
    const int   mytgt = tgt[i];
    const float sqi   = g_sq[i];

    const float INF_F = __int_as_float(0x7f800000);
    float maxv = -INF_F; int maxj = 0;
    float minv =  INF_F; int minj = 0;

    const int j0 = split * JRANGE;
    for (int jc = 0; jc < JRANGE; jc += TJ) {
        const int jbase = j0 + jc;
        __syncthreads();
        // Cooperative stage of TJ rows (TJ*64 floats) + targets + sq norms
        {
            const float4* src =
                reinterpret_cast<const float4*>(emb + (size_t)jbase * DIM);
            for (int k = threadIdx.x; k < TJ * (DIM / 4); k += ITILE)
                s_emb4[k] = src[k];
            if (threadIdx.x < TJ) {
                s_tgt[threadIdx.x] = tgt[jbase + threadIdx.x];
                s_sq[threadIdx.x]  = g_sq[jbase + threadIdx.x];
            }
        }
        __syncthreads();

#pragma unroll 1
        for (int jj = 0; jj < TJ; jj++) {
            const ulonglong2* b = reinterpret_cast<const ulonglong2*>(
                s_emb4 + jj * (DIM / 4));
            unsigned long long acc0 = 0ull, acc1 = 0ull,
                               acc2 = 0ull, acc3 = 0ull;
#pragma unroll
            for (int k = 0; k < DIM / 4; k += 2) {
                ulonglong2 b0 = b[k];
                ulonglong2 b1 = b[k + 1];
                FMA2(acc0, a[2 * k],     b0.x, acc0);
                FMA2(acc1, a[2 * k + 1], b0.y, acc1);
                FMA2(acc2, a[2 * k + 2], b1.x, acc2);
                FMA2(acc3, a[2 * k + 3], b1.y, acc3);
            }
            float l0, h0, l1, h1, l2, h2, l3, h3;
            UNPACK2(l0, h0, acc0);
            UNPACK2(l1, h1, acc1);
            UNPACK2(l2, h2, acc2);
            UNPACK2(l3, h3, acc3);
            float dot = ((l0 + h0) + (l1 + h1)) + ((l2 + h2) + (l3 + h3));

            float d = fmaxf(sqi + s_sq[jj] - 2.0f * dot, 0.0f);
            int j = jbase + jj;
            if (s_tgt[jj] == mytgt) {
                if (d > maxv) { maxv = d; maxj = j; }   // strict: first max
            } else {
                if (d < minv) { minv = d; minj = j; }   // strict: first min
            }
        }
    }

    const int o = split * N_ANCH + i;
    g_maxval[o] = maxv; g_maxidx[o] = maxj;
    g_minval[o] = minv; g_minidx[o] = minj;
}

// ---------------------------------------------------------------------------
// Kernel 2: combine splits (ascending order, strict compare => global
// first-occurrence), recompute exact ap/an, loss, deterministic block sum.
// ---------------------------------------------------------------------------
__global__ void loss_kernel(const float* __restrict__ emb) {
    __shared__ float red[256];
    const int i = blockIdx.x * 256 + threadIdx.x;

    const float INF_F = __int_as_float(0x7f800000);
    float maxv = -INF_F; int p = 0;
    float minv =  INF_F; int n = 0;
#pragma unroll
    for (int s = 0; s < NSPLIT; s++) {
        const int o = s * N_ANCH + i;
        float v = g_maxval[o];
        if (v > maxv) { maxv = v; p = g_maxidx[o]; }
        v = g_minval[o];
        if (v < minv) { minv = v; n = g_minidx[o]; }
    }

    const float4* ei = reinterpret_cast<const float4*>(emb + (size_t)i * DIM);
    const float4* ep = reinterpret_cast<const float4*>(emb + (size_t)p * DIM);
    const float4* en = reinterpret_cast<const float4*>(emb + (size_t)n * DIM);
    float ap = 0.f, an = 0.f;
#pragma unroll
    for (int k = 0; k < DIM / 4; k++) {
        float4 vi = ei[k], vp = ep[k], vn = en[k];
        float dx;
        dx = vi.x - vp.x; ap += dx * dx;
        dx = vi.y - vp.y; ap += dx * dx;
        dx = vi.z - vp.z; ap += dx * dx;
        dx = vi.w - vp.w; ap += dx * dx;
        dx = vi.x - vn.x; an += dx * dx;
        dx = vi.y - vn.y; an += dx * dx;
        dx = vi.z - vn.z; an += dx * dx;
        dx = vi.w - vn.w; an += dx * dx;
    }
    float loss = fmaxf(ap - an + MARGIN_F, 0.0f);

    // Deterministic tree reduce within the block
    red[threadIdx.x] = loss;
    __syncthreads();
#pragma unroll
    for (int off = 128; off > 0; off >>= 1) {
        if (threadIdx.x < off) red[threadIdx.x] += red[threadIdx.x + off];
        __syncthreads();
    }
    if (threadIdx.x == 0) g_partial[blockIdx.x] = red[0];
}

// ---------------------------------------------------------------------------
// Kernel 3: final mean (single thread; deterministic)
// ---------------------------------------------------------------------------
__global__ void final_kernel(float* __restrict__ out) {
    if (threadIdx.x == 0) {
        float s = 0.f;
#pragma unroll
        for (int k = 0; k < RBLOCKS; k++) s += g_partial[k];
        out[0] = s / (float)N_ANCH;
    }
}

// ---------------------------------------------------------------------------
extern "C" void kernel_launch(void* const* d_in, const int* in_sizes, int n_in,
                              void* d_out, int out_size) {
    const float* emb = (const float*)d_in[0];
    const int*   tgt = (const int*)d_in[1];
    float*       out = (float*)d_out;

    sqnorm_kernel<<<N_ANCH / 256, 256>>>(emb);
    dim3 grid(NITILES, NSPLIT);
    mine_kernel<<<grid, ITILE>>>(emb, tgt);
    loss_kernel<<<RBLOCKS, 256>>>(emb);
    final_kernel<<<1, 32>>>(out);
}